// round 9
// baseline (speedup 1.0000x reference)
#include <cuda_runtime.h>
#include <cuda_bf16.h>
#include <math.h>
#include <stdint.h>

#define BB 32
#define TF 2048
#define TP 256
#define FD 768
#define PD 512
#define AD 512
typedef __nv_bfloat16 bf16;
typedef __nv_bfloat162 bf162;

// ---------------- device scratch ----------------
__device__ float g_att[(size_t)BB * TF * AD];
__device__ bf16 g_f_hi[(size_t)BB * TF * FD], g_f_lo[(size_t)BB * TF * FD];
__device__ bf16 g_p_hi[(size_t)BB * TP * PD], g_p_lo[(size_t)BB * TP * PD];
__device__ bf16 g_wqt_hi[AD * FD], g_wqt_lo[AD * FD];
__device__ bf16 g_wkt_hi[AD * PD], g_wkt_lo[AD * PD];
__device__ bf16 g_q_hi[(size_t)BB * TF * AD], g_q_lo[(size_t)BB * TF * AD];
__device__ bf16 g_k_hi[(size_t)BB * TP * AD], g_k_lo[(size_t)BB * TP * AD];
__device__ bf16 g_kt_hi[(size_t)BB * AD * TP], g_kt_lo[(size_t)BB * AD * TP];
__device__ bf16 g_P_hi[(size_t)BB * TF * TP], g_P_lo[(size_t)BB * TF * TP];

// ---------------- helpers ----------------
__device__ __forceinline__ uint32_t s2u(const void* p) {
    uint32_t a;
    asm("{ .reg .u64 t; cvta.to.shared.u64 t, %1; cvt.u32.u64 %0, t; }"
        : "=r"(a) : "l"(p));
    return a;
}
__device__ __forceinline__ void split1(float v, bf16& h, bf16& l) {
    h = __float2bfloat16_rn(v);
    l = __float2bfloat16_rn(v - __bfloat162float(h));
}
__device__ __forceinline__ void cp16(uint32_t dst, const void* src) {
    asm volatile("cp.async.cg.shared.global [%0], [%1], 16;" :: "r"(dst), "l"(src));
}
__device__ __forceinline__ void cp_commit() { asm volatile("cp.async.commit_group;"); }
template <int N>
__device__ __forceinline__ void cp_wait() {
    asm volatile("cp.async.wait_group %0;" :: "n"(N));
}
__device__ __forceinline__ void ldm4(uint32_t* r, uint32_t addr) {
    asm volatile("ldmatrix.sync.aligned.m8n8.x4.shared.b16 {%0,%1,%2,%3}, [%4];"
                 : "=r"(r[0]), "=r"(r[1]), "=r"(r[2]), "=r"(r[3]) : "r"(addr));
}
__device__ __forceinline__ void mma16816(float* c, const uint32_t* a,
                                         uint32_t b0, uint32_t b1) {
    asm volatile("mma.sync.aligned.m16n8k16.row.col.f32.bf16.bf16.f32 "
                 "{%0,%1,%2,%3}, {%4,%5,%6,%7}, {%8,%9}, {%0,%1,%2,%3};"
                 : "+f"(c[0]), "+f"(c[1]), "+f"(c[2]), "+f"(c[3])
                 : "r"(a[0]), "r"(a[1]), "r"(a[2]), "r"(a[3]), "r"(b0), "r"(b1));
}
__device__ __forceinline__ float fexp(float x) {
    float y = fmaxf(x * 1.44269504f, -125.0f);
    float i = rintf(y);
    float f = y - i;
    float p = 1.3333558146e-3f;
    p = fmaf(p, f, 9.6181291076e-3f);
    p = fmaf(p, f, 5.5504108664e-2f);
    p = fmaf(p, f, 2.4022650696e-1f);
    p = fmaf(p, f, 6.9314718056e-1f);
    p = fmaf(p, f, 1.0f);
    float s = __int_as_float(((int)i + 127) << 23);
    return p * s;
}
// cp.async [ROWS x 64]bf16 K-major tile into XOR-swizzled smem; 256 threads
template <int ROWS>
__device__ __forceinline__ void ldt(const bf16* __restrict__ src, size_t row0,
                                    int ld, int k0, uint32_t dst, int t) {
#pragma unroll
    for (int it = 0; it < ROWS / 32; it++) {
        int u = it * 256 + t;
        int row = u >> 3, q = u & 7;
        cp16(dst + row * 128 + ((q ^ (row & 7)) << 4),
             src + (row0 + row) * (size_t)ld + k0 + q * 8);
    }
}

// ===== gemm_tc: C[128,128] = A[128,K] @ B[128,K]^T; 256 thr; 2 CTAs/SM =====
// Single 64KB stage (Ah|Al|Bh|Bl @16KB), phase-pipelined by q-unit pairs:
// phase pp covers q = {2*(pp&3), 2*(pp&3)+1} of chunk pp>>2; depth-3 in flight.
// MODE: 0 projQ, 1 projK(+K^T), 2 energy(+mask->outp), 3 att(->g_att)
#define GEMM_SMEM 65536
template <int MODE>
__global__ __launch_bounds__(256, 2)
void gemm_tc(const bf16* __restrict__ Ah, const bf16* __restrict__ Al, int lda,
             int sA, const bf16* __restrict__ Bh, const bf16* __restrict__ Bl,
             int ldb, int sB, int K, const void* __restrict__ aux,
             float* __restrict__ outp) {
    extern __shared__ char sm[];
    const uint32_t sbase = s2u(sm);
    const int t = threadIdx.x, lane = t & 31, wid = t >> 5;
    const int wm = wid >> 1, wn = wid & 1;  // 4 x 2 warps, warp tile 32 x 64
    const int b = blockIdx.z;
    const size_t arow0 = (size_t)b * sA + (size_t)blockIdx.y * 128;
    const size_t brow0 = (size_t)b * sB + (size_t)blockIdx.x * 128;
    const int NC = K / 64;
    const int NPH = NC * 4;

    float acc[2][8][4];
#pragma unroll
    for (int mt = 0; mt < 2; mt++)
#pragma unroll
        for (int nt = 0; nt < 8; nt++)
#pragma unroll
            for (int j = 0; j < 4; j++) acc[mt][nt][j] = 0.0f;

    // per-thread phase geometry: row = t>>1, q = 2*(pp&3) + (t&1)
    const int prow = t >> 1;
    const size_t aoff = (arow0 + prow) * (size_t)lda;
    const size_t boff = (brow0 + prow) * (size_t)ldb;

#define ISSUE_PHASE(pp_)                                                       \
    do {                                                                       \
        int _pp = (pp_);                                                       \
        if (_pp < NPH) {                                                       \
            int _q = ((_pp & 3) << 1) | (t & 1);                               \
            int _k = (_pp >> 2) * 64 + _q * 8;                                 \
            uint32_t _o = prow * 128 + ((_q ^ (prow & 7)) << 4);               \
            cp16(sbase + _o, Ah + aoff + _k);                                  \
            cp16(sbase + 16384 + _o, Al + aoff + _k);                          \
            cp16(sbase + 32768 + _o, Bh + boff + _k);                          \
            cp16(sbase + 49152 + _o, Bl + boff + _k);                          \
        }                                                                      \
        cp_commit();                                                           \
    } while (0)

    ISSUE_PHASE(0);
    ISSUE_PHASE(1);
    ISSUE_PHASE(2);

    for (int pp = 0; pp < NPH; pp++) {
        cp_wait<2>();       // phase pp arrived (groups complete in order)
        __syncthreads();    // ...visible to all; also: compute pp-1 done by all
        ISSUE_PHASE(pp + 3);  // refill region freed by compute pp-1
        const int ks = pp & 3;

        uint32_t ah[2][4], al[2][4], bh[8][2], bl[8][2];
#pragma unroll
        for (int mt = 0; mt < 2; mt++) {
            int row = wm * 32 + mt * 16 + (lane & 15);
            int q = ks * 2 + (lane >> 4);
            uint32_t off = row * 128 + ((q ^ (row & 7)) << 4);
            ldm4(ah[mt], sbase + off);
            ldm4(al[mt], sbase + 16384 + off);
        }
        const int g = lane >> 3, w = lane & 7;
#pragma unroll
        for (int np = 0; np < 4; np++) {
            int ntl = np * 2 + (g >> 1);
            int row = wn * 64 + ntl * 8 + w;
            int q = ks * 2 + (g & 1);
            uint32_t off = row * 128 + ((q ^ (row & 7)) << 4);
            uint32_t r4[4];
            ldm4(r4, sbase + 32768 + off);
            bh[np * 2][0] = r4[0]; bh[np * 2][1] = r4[1];
            bh[np * 2 + 1][0] = r4[2]; bh[np * 2 + 1][1] = r4[3];
            ldm4(r4, sbase + 49152 + off);
            bl[np * 2][0] = r4[0]; bl[np * 2][1] = r4[1];
            bl[np * 2 + 1][0] = r4[2]; bl[np * 2 + 1][1] = r4[3];
        }
#pragma unroll
        for (int mt = 0; mt < 2; mt++)
#pragma unroll
            for (int nt = 0; nt < 8; nt++) {
                mma16816(acc[mt][nt], ah[mt], bh[nt][0], bh[nt][1]);
                mma16816(acc[mt][nt], ah[mt], bl[nt][0], bl[nt][1]);
                mma16816(acc[mt][nt], al[mt], bh[nt][0], bh[nt][1]);
            }
    }
#undef ISSUE_PHASE

    // ---------------- epilogue ----------------
#pragma unroll
    for (int mt = 0; mt < 2; mt++)
#pragma unroll
        for (int h = 0; h < 2; h++) {
            const int rl = wm * 32 + mt * 16 + (lane >> 2) + h * 8;
#pragma unroll
            for (int nt = 0; nt < 8; nt++) {
                const int cl = wn * 64 + nt * 8 + (lane & 3) * 2;
                float v0 = acc[mt][nt][h * 2];
                float v1 = acc[mt][nt][h * 2 + 1];
                if (MODE == 0 || MODE == 1) {
                    const float* bias = (const float*)aux;
                    const size_t gr = (size_t)blockIdx.y * 128 + rl;
                    const int gc = blockIdx.x * 128 + cl;
                    v0 += bias[gc];
                    v1 += bias[gc + 1];
                    bf16 h0, l0, h1, l1;
                    split1(v0, h0, l0);
                    split1(v1, h1, l1);
                    bf162 ph; ph.x = h0; ph.y = h1;
                    bf162 pl; pl.x = l0; pl.y = l1;
                    if (MODE == 0) {
                        *(bf162*)&g_q_hi[gr * AD + gc] = ph;
                        *(bf162*)&g_q_lo[gr * AD + gc] = pl;
                    } else {
                        *(bf162*)&g_k_hi[gr * AD + gc] = ph;
                        *(bf162*)&g_k_lo[gr * AD + gc] = pl;
                        const int bb = (int)(gr >> 8), p = (int)(gr & 255);
                        g_kt_hi[((size_t)bb * AD + gc) * TP + p] = h0;
                        g_kt_lo[((size_t)bb * AD + gc) * TP + p] = l0;
                        g_kt_hi[((size_t)bb * AD + gc + 1) * TP + p] = h1;
                        g_kt_lo[((size_t)bb * AD + gc + 1) * TP + p] = l1;
                    }
                } else if (MODE == 2) {
                    const int* am = (const int*)aux;
                    const int mrow = blockIdx.y * 128 + rl;
                    const int gcol = blockIdx.x * 128 + cl;
                    v0 += (1.0f - (float)am[b * TP + gcol]) * (-1000.0f);
                    v1 += (1.0f - (float)am[b * TP + gcol + 1]) * (-1000.0f);
                    *(float2*)&outp[((size_t)b * TF + mrow) * TP + gcol] =
                        make_float2(v0, v1);
                } else {
                    const int mrow = blockIdx.y * 128 + rl;
                    const int gcol = blockIdx.x * 128 + cl;
                    *(float2*)&g_att[((size_t)b * TF + mrow) * AD + gcol] =
                        make_float2(v0, v1);
                }
            }
        }
}

// ---------------- pointwise kernels ----------------
__global__ void split_k(const float* __restrict__ in, bf16* __restrict__ hi,
                        bf16* __restrict__ lo, size_t n4) {
    size_t i = (size_t)blockIdx.x * blockDim.x + threadIdx.x;
    if (i >= n4) return;
    float4 v = ((const float4*)in)[i];
    bf16 h0, h1, h2, h3, l0, l1, l2, l3;
    split1(v.x, h0, l0); split1(v.y, h1, l1);
    split1(v.z, h2, l2); split1(v.w, h3, l3);
    bf162 a, b;
    a.x = h0; a.y = h1; b.x = h2; b.y = h3;
    ((bf162*)hi)[i * 2] = a; ((bf162*)hi)[i * 2 + 1] = b;
    a.x = l0; a.y = l1; b.x = l2; b.y = l3;
    ((bf162*)lo)[i * 2] = a; ((bf162*)lo)[i * 2 + 1] = b;
}
__global__ void tsplit_k(const float* __restrict__ W, bf16* __restrict__ hiT,
                         bf16* __restrict__ loT, int K, int N) {
    __shared__ float tile[32][33];
    const int n0 = blockIdx.x * 32, k0 = blockIdx.y * 32;
    for (int r = threadIdx.y; r < 32; r += 8)
        tile[r][threadIdx.x] = W[(size_t)(k0 + r) * N + n0 + threadIdx.x];
    __syncthreads();
    for (int r = threadIdx.y; r < 32; r += 8) {
        float v = tile[threadIdx.x][r];
        bf16 h, l;
        split1(v, h, l);
        hiT[(size_t)(n0 + r) * K + k0 + threadIdx.x] = h;
        loT[(size_t)(n0 + r) * K + k0 + threadIdx.x] = l;
    }
}
__global__ __launch_bounds__(256)
void softmax_k(const float* __restrict__ energy) {
    const int lane = threadIdx.x & 31, wid = threadIdx.x >> 5;
    const size_t row = (size_t)blockIdx.x * 8 + wid;
    const float* e = energy + row * TP + lane * 8;
    float v[8];
    *(float4*)&v[0] = *(const float4*)(e);
    *(float4*)&v[4] = *(const float4*)(e + 4);
    float mx = v[0];
#pragma unroll
    for (int j = 1; j < 8; j++) mx = fmaxf(mx, v[j]);
#pragma unroll
    for (int o = 16; o > 0; o >>= 1)
        mx = fmaxf(mx, __shfl_xor_sync(0xffffffffu, mx, o));
    float s = 0.0f;
#pragma unroll
    for (int j = 0; j < 8; j++) { v[j] = fexp(v[j] - mx); s += v[j]; }
#pragma unroll
    for (int o = 16; o > 0; o >>= 1)
        s += __shfl_xor_sync(0xffffffffu, s, o);
    const float inv = 1.0f / s;
    bf16* ph = g_P_hi + row * TP + lane * 8;
    bf16* pl = g_P_lo + row * TP + lane * 8;
#pragma unroll
    for (int j = 0; j < 8; j += 2) {
        bf16 h0, l0, h1, l1;
        split1(v[j] * inv, h0, l0);
        split1(v[j + 1] * inv, h1, l1);
        bf162 a; a.x = h0; a.y = h1; *(bf162*)(ph + j) = a;
        bf162 c; c.x = l0; c.y = l1; *(bf162*)(pl + j) = c;
    }
}
__global__ __launch_bounds__(256)
void ln_k(const float* __restrict__ gamma, const float* __restrict__ beta,
          float* __restrict__ att_out) {
    const int lane = threadIdx.x & 31, wid = threadIdx.x >> 5;
    const size_t row = (size_t)blockIdx.x * 8 + wid;
    const float4* arow = (const float4*)(g_att + row * AD) + lane * 4;
    float4 av[4];
    float qv[16];
    {
        const uint4 h0 = *(const uint4*)(g_q_hi + row * AD + lane * 16);
        const uint4 h1 = *(const uint4*)(g_q_hi + row * AD + lane * 16 + 8);
        const uint4 l0 = *(const uint4*)(g_q_lo + row * AD + lane * 16);
        const uint4 l1 = *(const uint4*)(g_q_lo + row * AD + lane * 16 + 8);
        const uint32_t hw[8] = {h0.x, h0.y, h0.z, h0.w, h1.x, h1.y, h1.z, h1.w};
        const uint32_t lw[8] = {l0.x, l0.y, l0.z, l0.w, l1.x, l1.y, l1.z, l1.w};
#pragma unroll
        for (int j = 0; j < 8; j++) {
            bf162 h = *(const bf162*)&hw[j];
            bf162 l = *(const bf162*)&lw[j];
            qv[2 * j]     = __bfloat162float(h.x) + __bfloat162float(l.x);
            qv[2 * j + 1] = __bfloat162float(h.y) + __bfloat162float(l.y);
        }
    }
    float s = 0.0f, ss = 0.0f;
#pragma unroll
    for (int u = 0; u < 4; u++) {
        av[u] = arow[u];
        s += av[u].x + av[u].y + av[u].z + av[u].w;
        ss = fmaf(av[u].x, av[u].x, ss); ss = fmaf(av[u].y, av[u].y, ss);
        ss = fmaf(av[u].z, av[u].z, ss); ss = fmaf(av[u].w, av[u].w, ss);
    }
#pragma unroll
    for (int j = 0; j < 16; j++) {
        s += qv[j];
        ss = fmaf(qv[j], qv[j], ss);
    }
#pragma unroll
    for (int o = 16; o > 0; o >>= 1) {
        s  += __shfl_xor_sync(0xffffffffu, s, o);
        ss += __shfl_xor_sync(0xffffffffu, ss, o);
    }
    const float mu = s * (1.0f / 1024.0f);
    const float var = ss * (1.0f / 1024.0f) - mu * mu;
    const float rs = rsqrtf(var + 1e-5f);
    float* orow = att_out + row * 1024;
#pragma unroll
    for (int u = 0; u < 4; u++) {
        int c = lane * 16 + u * 4;
        float4 g = *(const float4*)(gamma + c);
        float4 be = *(const float4*)(beta + c);
        float4 o;
        o.x = (av[u].x - mu) * rs * g.x + be.x;
        o.y = (av[u].y - mu) * rs * g.y + be.y;
        o.z = (av[u].z - mu) * rs * g.z + be.z;
        o.w = (av[u].w - mu) * rs * g.w + be.w;
        *(float4*)(orow + c) = o;
        int c2 = AD + c;
        g = *(const float4*)(gamma + c2);
        be = *(const float4*)(beta + c2);
        o.x = (qv[u * 4]     - mu) * rs * g.x + be.x;
        o.y = (qv[u * 4 + 1] - mu) * rs * g.y + be.y;
        o.z = (qv[u * 4 + 2] - mu) * rs * g.z + be.z;
        o.w = (qv[u * 4 + 3] - mu) * rs * g.w + be.w;
        *(float4*)(orow + c2) = o;
    }
}

// ---------------------------------------------------------------------------
extern "C" void kernel_launch(void* const* d_in, const int* in_sizes, int n_in,
                              void* d_out, int out_size) {
    const float* frame = (const float*)d_in[0];
    const float* phn   = (const float*)d_in[1];
    const int*   amask = (const int*)  d_in[2];
    const float* Wq    = (const float*)d_in[3];
    const float* bq    = (const float*)d_in[4];
    const float* Wk    = (const float*)d_in[5];
    const float* bk    = (const float*)d_in[6];
    const float* gamma = (const float*)d_in[7];
    const float* beta  = (const float*)d_in[8];

    float* out        = (float*)d_out;
    float* att_out    = out;
    float* energy_out = out + ((size_t)out_size - (size_t)BB * TF * TP);

    cudaFuncSetAttribute(gemm_tc<0>, cudaFuncAttributeMaxDynamicSharedMemorySize, GEMM_SMEM);
    cudaFuncSetAttribute(gemm_tc<1>, cudaFuncAttributeMaxDynamicSharedMemorySize, GEMM_SMEM);
    cudaFuncSetAttribute(gemm_tc<2>, cudaFuncAttributeMaxDynamicSharedMemorySize, GEMM_SMEM);
    cudaFuncSetAttribute(gemm_tc<3>, cudaFuncAttributeMaxDynamicSharedMemorySize, GEMM_SMEM);

    bf16 *fh, *fl, *ph_, *pl_, *wqh, *wql, *wkh, *wkl;
    bf16 *qh, *ql, *kh, *kl, *kth, *ktl, *Ph, *Pl;
    cudaGetSymbolAddress((void**)&fh, g_f_hi);
    cudaGetSymbolAddress((void**)&fl, g_f_lo);
    cudaGetSymbolAddress((void**)&ph_, g_p_hi);
    cudaGetSymbolAddress((void**)&pl_, g_p_lo);
    cudaGetSymbolAddress((void**)&wqh, g_wqt_hi);
    cudaGetSymbolAddress((void**)&wql, g_wqt_lo);
    cudaGetSymbolAddress((void**)&wkh, g_wkt_hi);
    cudaGetSymbolAddress((void**)&wkl, g_wkt_lo);
    cudaGetSymbolAddress((void**)&qh, g_q_hi);
    cudaGetSymbolAddress((void**)&ql, g_q_lo);
    cudaGetSymbolAddress((void**)&kh, g_k_hi);
    cudaGetSymbolAddress((void**)&kl, g_k_lo);
    cudaGetSymbolAddress((void**)&kth, g_kt_hi);
    cudaGetSymbolAddress((void**)&ktl, g_kt_lo);
    cudaGetSymbolAddress((void**)&Ph, g_P_hi);
    cudaGetSymbolAddress((void**)&Pl, g_P_lo);

    {
        size_t n4 = (size_t)BB * TF * FD / 4;
        split_k<<<(unsigned)(n4 / 256), 256>>>(frame, fh, fl, n4);
    }
    {
        size_t n4 = (size_t)BB * TP * PD / 4;
        split_k<<<(unsigned)(n4 / 256), 256>>>(phn, ph_, pl_, n4);
    }
    tsplit_k<<<dim3(AD / 32, FD / 32), dim3(32, 8)>>>(Wq, wqh, wql, FD, AD);
    tsplit_k<<<dim3(AD / 32, PD / 32), dim3(32, 8)>>>(Wk, wkh, wkl, PD, AD);

    // projections
    gemm_tc<1><<<dim3(4, 64, 1), 256, GEMM_SMEM>>>(ph_, pl_, PD, 0, wkh, wkl,
                                                   PD, 0, PD, bk, nullptr);
    gemm_tc<0><<<dim3(4, 512, 1), 256, GEMM_SMEM>>>(fh, fl, FD, 0, wqh, wql,
                                                    FD, 0, FD, bq, nullptr);

    // energy = q @ k^T + mask
    gemm_tc<2><<<dim3(2, 16, BB), 256, GEMM_SMEM>>>(qh, ql, AD, TF, kh, kl,
                                                    AD, TP, AD, amask, energy_out);
    // softmax -> P hi/lo
    softmax_k<<<BB * TF / 8, 256>>>(energy_out);
    // att = P @ k
    gemm_tc<3><<<dim3(4, 16, BB), 256, GEMM_SMEM>>>(Ph, Pl, TP, TF, kth, ktl,
                                                    TP, AD, TP, nullptr, nullptr);
    // LayerNorm
    ln_k<<<BB * TF / 8, 256>>>(gamma, beta, att_out);
}

// round 10
// speedup vs baseline: 1.2961x; 1.2961x over previous
#include <cuda_runtime.h>
#include <cuda_bf16.h>
#include <math.h>
#include <stdint.h>

#define BB 32
#define TF 2048
#define TP 256
#define FD 768
#define PD 512
#define AD 512

// ---------------- device scratch (all fp32; tf32-rounded where noted) -------
__device__ float g_f[(size_t)BB * TF * FD];    // rounded frame
__device__ float g_pn[(size_t)BB * TP * PD];   // rounded phn
__device__ float g_wqt[AD * FD];               // rounded Wq^T
__device__ float g_wkt[AD * PD];               // rounded Wk^T
__device__ float g_q[(size_t)BB * TF * AD];    // FULL fp32 (output path)
__device__ float g_k[(size_t)BB * TP * AD];    // rounded
__device__ float g_kt[(size_t)BB * AD * TP];   // rounded
__device__ float g_P[(size_t)BB * TF * TP];    // rounded
__device__ float g_att[(size_t)BB * TF * AD];  // full fp32

// ---------------- helpers ----------------
__device__ __forceinline__ uint32_t s2u(const void* p) {
    uint32_t a;
    asm("{ .reg .u64 t; cvta.to.shared.u64 t, %1; cvt.u32.u64 %0, t; }"
        : "=r"(a) : "l"(p));
    return a;
}
__device__ __forceinline__ float rnd_tf32(float x) {
    uint32_t u;
    asm("cvt.rna.tf32.f32 %0, %1;" : "=r"(u) : "f"(x));
    return __uint_as_float(u);
}
__device__ __forceinline__ void cp16(uint32_t dst, const void* src) {
    asm volatile("cp.async.cg.shared.global [%0], [%1], 16;" :: "r"(dst), "l"(src));
}
__device__ __forceinline__ void cp_commit() { asm volatile("cp.async.commit_group;"); }
template <int N>
__device__ __forceinline__ void cp_wait() {
    asm volatile("cp.async.wait_group %0;" :: "n"(N));
}
__device__ __forceinline__ void lds32(uint32_t& x, uint32_t addr) {
    asm volatile("ld.shared.b32 %0, [%1];" : "=r"(x) : "r"(addr));
}
__device__ __forceinline__ void mma_tf32(float* c, const uint32_t* a,
                                         uint32_t b0, uint32_t b1) {
    asm volatile("mma.sync.aligned.m16n8k8.row.col.f32.tf32.tf32.f32 "
                 "{%0,%1,%2,%3}, {%4,%5,%6,%7}, {%8,%9}, {%0,%1,%2,%3};"
                 : "+f"(c[0]), "+f"(c[1]), "+f"(c[2]), "+f"(c[3])
                 : "r"(a[0]), "r"(a[1]), "r"(a[2]), "r"(a[3]), "r"(b0), "r"(b1));
}
__device__ __forceinline__ float fexp(float x) {
    float y = fmaxf(x * 1.44269504f, -125.0f);
    float i = rintf(y);
    float f = y - i;
    float p = 1.3333558146e-3f;
    p = fmaf(p, f, 9.6181291076e-3f);
    p = fmaf(p, f, 5.5504108664e-2f);
    p = fmaf(p, f, 2.4022650696e-1f);
    p = fmaf(p, f, 6.9314718056e-1f);
    p = fmaf(p, f, 1.0f);
    float s = __int_as_float(((int)i + 127) << 23);
    return p * s;
}
// cp.async [128 x 32]fp32 tile (row-major, ld floats) into swizzled smem.
// Row = 32 floats = 128B = 8x16B units; unit q XORed with (row&7).
__device__ __forceinline__ void ldt32(const float* __restrict__ src, size_t row0,
                                      int ld, int k0, uint32_t dst, int t) {
#pragma unroll
    for (int it = 0; it < 4; it++) {
        int u = it * 256 + t;
        int row = u >> 3, q = u & 7;
        cp16(dst + row * 128 + ((q ^ (row & 7)) << 4),
             src + (row0 + row) * (size_t)ld + k0 + q * 4);
    }
}

// ==== gemm_tf32: C[128,128] = A[128,K] @ B[128,K]^T; BK=32 double-buffered;
//      256 threads, 2 CTAs/SM. MODE: 0 projQ, 1 projK(+K^T), 2 energy, 3 att.
#define GEMM_SMEM 65536
template <int MODE>
__global__ __launch_bounds__(256, 2)
void gemm_tf32(const float* __restrict__ A, int lda, int sA,
               const float* __restrict__ B, int ldb, int sB, int K,
               const void* __restrict__ aux, float* __restrict__ outp) {
    extern __shared__ char sm[];
    const uint32_t sbase = s2u(sm);
    const int t = threadIdx.x, lane = t & 31, wid = t >> 5;
    const int wm = wid >> 1, wn = wid & 1;  // 4 x 2 warps, warp tile 32 x 64
    const int b = blockIdx.z;
    const size_t arow0 = (size_t)b * sA + (size_t)blockIdx.y * 128;
    const size_t brow0 = (size_t)b * sB + (size_t)blockIdx.x * 128;
    const int NC = K / 32;

    float acc[2][8][4];
#pragma unroll
    for (int mt = 0; mt < 2; mt++)
#pragma unroll
        for (int nt = 0; nt < 8; nt++)
#pragma unroll
            for (int j = 0; j < 4; j++) acc[mt][nt][j] = 0.0f;

    ldt32(A, arow0, lda, 0, sbase, t);
    ldt32(B, brow0, ldb, 0, sbase + 16384, t);
    cp_commit();

    for (int c = 0; c < NC; c++) {
        if (c + 1 < NC) {
            uint32_t sn = sbase + ((c + 1) & 1) * 32768;
            ldt32(A, arow0, lda, (c + 1) * 32, sn, t);
            ldt32(B, brow0, ldb, (c + 1) * 32, sn + 16384, t);
            cp_commit();
            cp_wait<1>();
        } else {
            cp_wait<0>();
        }
        __syncthreads();
        const uint32_t sa = sbase + (c & 1) * 32768;
        const uint32_t sb = sa + 16384;
        const uint32_t cofs = (lane & 3) << 2;
#pragma unroll
        for (int ks = 0; ks < 4; ks++) {
            const uint32_t q0s = (uint32_t)(2 * ks), q1s = (uint32_t)(2 * ks + 1);
            uint32_t a[2][4];
#pragma unroll
            for (int mt = 0; mt < 2; mt++) {
                int r0_ = wm * 32 + mt * 16 + (lane >> 2);
                int r1_ = r0_ + 8;
                uint32_t base0 = sa + r0_ * 128 + cofs;
                uint32_t base1 = sa + r1_ * 128 + cofs;
                lds32(a[mt][0], base0 + ((q0s ^ (r0_ & 7)) << 4));
                lds32(a[mt][1], base1 + ((q0s ^ (r1_ & 7)) << 4));
                lds32(a[mt][2], base0 + ((q1s ^ (r0_ & 7)) << 4));
                lds32(a[mt][3], base1 + ((q1s ^ (r1_ & 7)) << 4));
            }
            if (MODE == 2) {
#pragma unroll
                for (int mt = 0; mt < 2; mt++)
#pragma unroll
                    for (int j = 0; j < 4; j++) {
                        float f = __uint_as_float(a[mt][j]);
                        asm("cvt.rna.tf32.f32 %0, %1;" : "=r"(a[mt][j]) : "f"(f));
                    }
            }
#pragma unroll
            for (int nt = 0; nt < 8; nt++) {
                int br = wn * 64 + nt * 8 + (lane >> 2);
                uint32_t baseb = sb + br * 128 + cofs;
                uint32_t b0, b1;
                lds32(b0, baseb + ((q0s ^ (br & 7)) << 4));
                lds32(b1, baseb + ((q1s ^ (br & 7)) << 4));
                mma_tf32(acc[0][nt], a[0], b0, b1);
                mma_tf32(acc[1][nt], a[1], b0, b1);
            }
        }
        __syncthreads();
    }

    // ---------------- epilogue ----------------
#pragma unroll
    for (int mt = 0; mt < 2; mt++)
#pragma unroll
        for (int h = 0; h < 2; h++) {
            const int rl = wm * 32 + mt * 16 + (lane >> 2) + h * 8;
#pragma unroll
            for (int nt = 0; nt < 8; nt++) {
                const int cl = wn * 64 + nt * 8 + (lane & 3) * 2;
                float v0 = acc[mt][nt][h * 2];
                float v1 = acc[mt][nt][h * 2 + 1];
                if (MODE == 0 || MODE == 1) {
                    const float* bias = (const float*)aux;
                    const size_t gr = (size_t)blockIdx.y * 128 + rl;
                    const int gc = blockIdx.x * 128 + cl;
                    v0 += bias[gc];
                    v1 += bias[gc + 1];
                    if (MODE == 0) {
                        // full fp32 (output path); energy GEMM rounds in-loop
                        *(float2*)&g_q[gr * AD + gc] = make_float2(v0, v1);
                    } else {
                        float r0 = rnd_tf32(v0), r1 = rnd_tf32(v1);
                        *(float2*)&g_k[gr * AD + gc] = make_float2(r0, r1);
                        const int bb = (int)(gr >> 8), p = (int)(gr & 255);
                        g_kt[((size_t)bb * AD + gc) * TP + p] = r0;
                        g_kt[((size_t)bb * AD + gc + 1) * TP + p] = r1;
                    }
                } else if (MODE == 2) {
                    const int* am = (const int*)aux;
                    const int mrow = blockIdx.y * 128 + rl;
                    const int gcol = blockIdx.x * 128 + cl;
                    v0 += (1.0f - (float)am[b * TP + gcol]) * (-1000.0f);
                    v1 += (1.0f - (float)am[b * TP + gcol + 1]) * (-1000.0f);
                    *(float2*)&outp[((size_t)b * TF + mrow) * TP + gcol] =
                        make_float2(v0, v1);
                } else {
                    const int mrow = blockIdx.y * 128 + rl;
                    const int gcol = blockIdx.x * 128 + cl;
                    *(float2*)&g_att[((size_t)b * TF + mrow) * AD + gcol] =
                        make_float2(v0, v1);
                }
            }
        }
}

// ---------------- pointwise kernels ----------------
__global__ void round_k(const float* __restrict__ in, float* __restrict__ out,
                        size_t n4) {
    size_t i = (size_t)blockIdx.x * blockDim.x + threadIdx.x;
    if (i >= n4) return;
    float4 v = ((const float4*)in)[i];
    v.x = rnd_tf32(v.x);
    v.y = rnd_tf32(v.y);
    v.z = rnd_tf32(v.z);
    v.w = rnd_tf32(v.w);
    ((float4*)out)[i] = v;
}
// transpose + round: W [K,N] -> W^T [N,K]
__global__ void twt_k(const float* __restrict__ W, float* __restrict__ WT,
                      int K, int N) {
    __shared__ float tile[32][33];
    const int n0 = blockIdx.x * 32, k0 = blockIdx.y * 32;
    for (int r = threadIdx.y; r < 32; r += 8)
        tile[r][threadIdx.x] = W[(size_t)(k0 + r) * N + n0 + threadIdx.x];
    __syncthreads();
    for (int r = threadIdx.y; r < 32; r += 8)
        WT[(size_t)(n0 + r) * K + k0 + threadIdx.x] = rnd_tf32(tile[threadIdx.x][r]);
}
__global__ __launch_bounds__(256)
void softmax_k(const float* __restrict__ energy) {
    const int lane = threadIdx.x & 31, wid = threadIdx.x >> 5;
    const size_t row = (size_t)blockIdx.x * 8 + wid;
    const float* e = energy + row * TP + lane * 8;
    float v[8];
    *(float4*)&v[0] = *(const float4*)(e);
    *(float4*)&v[4] = *(const float4*)(e + 4);
    float mx = v[0];
#pragma unroll
    for (int j = 1; j < 8; j++) mx = fmaxf(mx, v[j]);
#pragma unroll
    for (int o = 16; o > 0; o >>= 1)
        mx = fmaxf(mx, __shfl_xor_sync(0xffffffffu, mx, o));
    float s = 0.0f;
#pragma unroll
    for (int j = 0; j < 8; j++) { v[j] = fexp(v[j] - mx); s += v[j]; }
#pragma unroll
    for (int o = 16; o > 0; o >>= 1)
        s += __shfl_xor_sync(0xffffffffu, s, o);
    const float inv = 1.0f / s;
    float* pp = g_P + row * TP + lane * 8;
#pragma unroll
    for (int j = 0; j < 8; j += 4) {
        float4 o;
        o.x = rnd_tf32(v[j] * inv);
        o.y = rnd_tf32(v[j + 1] * inv);
        o.z = rnd_tf32(v[j + 2] * inv);
        o.w = rnd_tf32(v[j + 3] * inv);
        *(float4*)(pp + j) = o;
    }
}
__global__ __launch_bounds__(256)
void ln_k(const float* __restrict__ gamma, const float* __restrict__ beta,
          float* __restrict__ att_out) {
    const int lane = threadIdx.x & 31, wid = threadIdx.x >> 5;
    const size_t row = (size_t)blockIdx.x * 8 + wid;
    const float4* arow = (const float4*)(g_att + row * AD) + lane * 4;
    const float4* qrow = (const float4*)(g_q + row * AD) + lane * 4;
    float4 av[4], qv[4];
    float s = 0.0f, ss = 0.0f;
#pragma unroll
    for (int u = 0; u < 4; u++) {
        av[u] = arow[u];
        qv[u] = qrow[u];
        s += av[u].x + av[u].y + av[u].z + av[u].w;
        s += qv[u].x + qv[u].y + qv[u].z + qv[u].w;
        ss = fmaf(av[u].x, av[u].x, ss); ss = fmaf(av[u].y, av[u].y, ss);
        ss = fmaf(av[u].z, av[u].z, ss); ss = fmaf(av[u].w, av[u].w, ss);
        ss = fmaf(qv[u].x, qv[u].x, ss); ss = fmaf(qv[u].y, qv[u].y, ss);
        ss = fmaf(qv[u].z, qv[u].z, ss); ss = fmaf(qv[u].w, qv[u].w, ss);
    }
#pragma unroll
    for (int o = 16; o > 0; o >>= 1) {
        s  += __shfl_xor_sync(0xffffffffu, s, o);
        ss += __shfl_xor_sync(0xffffffffu, ss, o);
    }
    const float mu = s * (1.0f / 1024.0f);
    const float var = ss * (1.0f / 1024.0f) - mu * mu;
    const float rs = rsqrtf(var + 1e-5f);
    float* orow = att_out + row * 1024;
#pragma unroll
    for (int u = 0; u < 4; u++) {
        int c = lane * 16 + u * 4;
        float4 g = *(const float4*)(gamma + c);
        float4 be = *(const float4*)(beta + c);
        float4 o;
        o.x = (av[u].x - mu) * rs * g.x + be.x;
        o.y = (av[u].y - mu) * rs * g.y + be.y;
        o.z = (av[u].z - mu) * rs * g.z + be.z;
        o.w = (av[u].w - mu) * rs * g.w + be.w;
        *(float4*)(orow + c) = o;
        int c2 = AD + c;
        g = *(const float4*)(gamma + c2);
        be = *(const float4*)(beta + c2);
        o.x = (qv[u].x - mu) * rs * g.x + be.x;
        o.y = (qv[u].y - mu) * rs * g.y + be.y;
        o.z = (qv[u].z - mu) * rs * g.z + be.z;
        o.w = (qv[u].w - mu) * rs * g.w + be.w;
        *(float4*)(orow + c2) = o;
    }
}

// ---------------------------------------------------------------------------
extern "C" void kernel_launch(void* const* d_in, const int* in_sizes, int n_in,
                              void* d_out, int out_size) {
    const float* frame = (const float*)d_in[0];
    const float* phn   = (const float*)d_in[1];
    const int*   amask = (const int*)  d_in[2];
    const float* Wq    = (const float*)d_in[3];
    const float* bq    = (const float*)d_in[4];
    const float* Wk    = (const float*)d_in[5];
    const float* bk    = (const float*)d_in[6];
    const float* gamma = (const float*)d_in[7];
    const float* beta  = (const float*)d_in[8];

    float* out        = (float*)d_out;
    float* att_out    = out;
    float* energy_out = out + ((size_t)out_size - (size_t)BB * TF * TP);

    cudaFuncSetAttribute(gemm_tf32<0>, cudaFuncAttributeMaxDynamicSharedMemorySize, GEMM_SMEM);
    cudaFuncSetAttribute(gemm_tf32<1>, cudaFuncAttributeMaxDynamicSharedMemorySize, GEMM_SMEM);
    cudaFuncSetAttribute(gemm_tf32<2>, cudaFuncAttributeMaxDynamicSharedMemorySize, GEMM_SMEM);
    cudaFuncSetAttribute(gemm_tf32<3>, cudaFuncAttributeMaxDynamicSharedMemorySize, GEMM_SMEM);

    float *gf, *gp, *gwq, *gwk, *gq, *gk, *gkt, *gP;
    cudaGetSymbolAddress((void**)&gf, g_f);
    cudaGetSymbolAddress((void**)&gp, g_pn);
    cudaGetSymbolAddress((void**)&gwq, g_wqt);
    cudaGetSymbolAddress((void**)&gwk, g_wkt);
    cudaGetSymbolAddress((void**)&gq, g_q);
    cudaGetSymbolAddress((void**)&gk, g_k);
    cudaGetSymbolAddress((void**)&gkt, g_kt);
    cudaGetSymbolAddress((void**)&gP, g_P);

    {
        size_t n4 = (size_t)BB * TF * FD / 4;
        round_k<<<(unsigned)(n4 / 256), 256>>>(frame, gf, n4);
    }
    {
        size_t n4 = (size_t)BB * TP * PD / 4;
        round_k<<<(unsigned)(n4 / 256), 256>>>(phn, gp, n4);
    }
    twt_k<<<dim3(AD / 32, FD / 32), dim3(32, 8)>>>(Wq, gwq, FD, AD);
    twt_k<<<dim3(AD / 32, PD / 32), dim3(32, 8)>>>(Wk, gwk, PD, AD);

    // projections
    gemm_tf32<1><<<dim3(4, 64, 1), 256, GEMM_SMEM>>>(gp, PD, 0, gwk, PD, 0,
                                                     PD, bk, nullptr);
    gemm_tf32<0><<<dim3(4, 512, 1), 256, GEMM_SMEM>>>(gf, FD, 0, gwq, FD, 0,
                                                      FD, bq, nullptr);

    // energy = q @ k^T + mask (A rounded in-loop)
    gemm_tf32<2><<<dim3(2, 16, BB), 256, GEMM_SMEM>>>(gq, AD, TF, gk, AD, TP,
                                                      AD, amask, energy_out);
    // softmax -> P (rounded)
    softmax_k<<<BB * TF / 8, 256>>>(energy_out);
    // att = P @ k
    gemm_tf32<3><<<dim3(4, 16, BB), 256, GEMM_SMEM>>>(gP, TP, TF, gkt, TP, AD,
                                                      TP, nullptr, nullptr);
    // LayerNorm
    ln_k<<<BB * TF / 8, 256>>>(gamma, beta, att_out);
}